// round 8
// baseline (speedup 1.0000x reference)
#include <cuda_runtime.h>

// Block-diagonal grouped conv2d: 64 groups, 4 in-ch -> 4 out-ch per group, 3x3, pad 1.
// x:   (32, 256, 128, 128) fp32, channel index = ci*64 + head
// w:   (64, 4, 4, 3, 3)          w[head][co][ci][ky][kx]
// b:   (64, 4)
// out: (32, 256, 128, 128) fp32, channel index = co*64 + head
//
// v8 = v6 (TY=8, 128 thr, 7 CTAs/SM, swizzled smem, f32x2 FMA) with the
//      shuffle/select edge chain replaced by independent scalar LDS reads;
//      j-boundary edges read pre-zeroed gap slots of the swizzled layout.

#define TY 8
#define SROWS (TY + 2)               // 10
#define SROW_P 188                   // phys floats per row (swizzle pad)
#define PLANE_P (SROWS * SROW_P)     // 1880
#define S_IN_FLOATS (4 * PLANE_P)    // 7520
#define THREADS 128
#define H 128
#define W 128
#define PLANE (H * W)
#define SMEM_BYTES ((S_IN_FLOATS + 2 * 144 + 4) * 4)

typedef unsigned long long u64;

__device__ __forceinline__ u64 pk(float lo, float hi) {
    u64 r; asm("mov.b64 %0, {%1, %2};" : "=l"(r) : "f"(lo), "f"(hi)); return r;
}
// d += a*b  (packed 2x fp32)
__device__ __forceinline__ void ffma2(u64 &d, u64 a, u64 b) {
    asm("fma.rn.f32x2 %0, %1, %2, %0;" : "+l"(d) : "l"(a), "l"(b));
}

union F4 { float4 f; ulonglong2 u; };

__global__ __launch_bounds__(THREADS, 7)
void bdconv_kernel(const float* __restrict__ x, const float* __restrict__ w,
                   const float* __restrict__ bias, float* __restrict__ out) {
    extern __shared__ __align__(16) float smem[];
    float* s_in   = smem;                        // [ci][r][phys-col]
    u64*   s_w    = (u64*)(smem + S_IN_FLOATS);  // [ci][ky][kx][co], dup halves
    float* s_bias = (float*)(s_w + 144);

    const int blk  = blockIdx.x;
    const int tile = blk & 15;          // 16 row-tiles of 8
    const int head = (blk >> 4) & 63;
    const int b    = blk >> 10;
    const int y0   = tile * TY;
    const int tid  = threadIdx.x;
    const int wrp  = tid >> 5;
    const int lane = tid & 31;

    // ---- stage weights (duplicated into f32x2 lanes) + bias ----
    for (int t = tid; t < 144; t += THREADS) {
        const int co  = t / 36;
        const int rem = t % 36;
        const int ci  = rem / 9;
        const int tt  = rem % 9;        // ky*3+kx
        const float wv = w[((head * 4 + co) * 4 + ci) * 9 + tt];
        s_w[(ci * 9 + tt) * 4 + co] = pk(wv, wv);
    }
    if (tid < 4) s_bias[tid] = bias[head * 4 + tid];

    // ---- zero the edge gap slots (phys 8,9 of every row; never written by stage) ----
    for (int t = tid; t < 4 * SROWS * 2; t += THREADS) {   // 80 floats
        const int row  = t >> 1;                           // 0..39 = ci*10 + r
        const int side = t & 1;
        smem[row * SROW_P + 8 + side] = 0.0f;
    }

    // ---- stage input: 4 warps x 10 warp-rows (40 = 4ci x 10 rows) ----
    // lane->chunk permutation keeps STS.128 conflict-free under the swizzle:
    //   lanes 0-15  -> even chunks  (phys chunk sigma = 3l)
    //   lanes 16-31 -> odd  chunks  (phys chunk sigma = 3m+1)
    int x0, sig;
    if (lane < 16) { x0 = lane << 3;              sig = 3 * lane; }
    else           { x0 = ((lane - 16) << 3) + 4; sig = 3 * (lane - 16) + 1; }
    const float* xb = x + ((long long)b * 256 + head) * PLANE;   // ci stride 64*PLANE
    #pragma unroll
    for (int k = 0; k < 10; k++) {
        const int rr = wrp + (k << 2);            // 0..39
        const int ci = rr / SROWS;
        const int r  = rr - ci * SROWS;
        const int y  = y0 - 1 + r;
        float4 v = make_float4(0.f, 0.f, 0.f, 0.f);
        if (y >= 0 && y < H)
            v = *(const float4*)(xb + ci * (64 * PLANE) + y * W + x0);
        *(float4*)(s_in + ci * PLANE_P + r * SROW_P + (sig << 2)) = v;
    }
    __syncthreads();

    // ---- compute: each thread = 8 pixels x 4 out-channels ----
    const int r  = tid >> 4;           // row within tile, 0..7
    const int j  = tid & 15;           // pixel-octet index, x = 8j..8j+7
    const int rbase = r * SROW_P;
    const int base  = rbase + 12 * j;  // phys(8j) = 12j
    // edge scalar addresses, loop-invariant (boundary lanes hit zeroed gap slots)
    const int Abase = rbase + ((j == 0)  ? 8 : (12 * j - 5));        // x = 8j-1
    const int Dbase = rbase + ((j == 15) ? 9 : (12 * (j + 1)));      // x = 8j+8

    u64 acc[4][4];                     // [co][pixel-pair]
    #pragma unroll
    for (int co = 0; co < 4; co++) {
        const float bv = s_bias[co];
        const u64 bp = pk(bv, bv);
        #pragma unroll
        for (int q = 0; q < 4; q++) acc[co][q] = bp;
    }

    #pragma unroll
    for (int ci = 0; ci < 4; ci++) {
        #pragma unroll
        for (int ky = 0; ky < 3; ky++) {
            const int imm = ci * PLANE_P + ky * SROW_P;   // compile-time
            F4 B, C;
            B.f = *(const float4*)(s_in + imm + base);
            C.f = *(const float4*)(s_in + imm + base + 4);
            const float A = s_in[imm + Abase];
            const float D = s_in[imm + Dbase];

            // 9 adjacent pairs of window x(8j-1 .. 8j+8)
            u64 p[9];
            p[0] = pk(A,     B.f.x);
            p[1] = B.u.x;
            p[2] = pk(B.f.y, B.f.z);
            p[3] = B.u.y;
            p[4] = pk(B.f.w, C.f.x);
            p[5] = C.u.x;
            p[6] = pk(C.f.y, C.f.z);
            p[7] = C.u.y;
            p[8] = pk(C.f.w, D);

            // weights: 6 x LDS.128 uniform broadcast -> [kx][co]
            const ulonglong2* wp = (const ulonglong2*)(s_w + (ci * 9 + ky * 3) * 4);
            ulonglong2 wv[6];
            #pragma unroll
            for (int t = 0; t < 6; t++) wv[t] = wp[t];

            // 48 packed FMAs
            #pragma unroll
            for (int q = 0; q < 4; q++)
                #pragma unroll
                for (int kx = 0; kx < 3; kx++) {
                    const u64 in = p[2 * q + kx];
                    ffma2(acc[0][q], wv[kx * 2 + 0].x, in);
                    ffma2(acc[1][q], wv[kx * 2 + 0].y, in);
                    ffma2(acc[2][q], wv[kx * 2 + 1].x, in);
                    ffma2(acc[3][q], wv[kx * 2 + 1].y, in);
                }
        }
    }

    // ---- store: coalesced 2x STG.128 per co ----
    const int y = y0 + r;
    float* obase = out + (((long long)b * 256 + head) * H + y) * W + (j << 3);
    #pragma unroll
    for (int co = 0; co < 4; co++) {
        ulonglong2* dst = (ulonglong2*)(obase + (long long)co * (64 * PLANE));
        ulonglong2 s0, s1;
        s0.x = acc[co][0]; s0.y = acc[co][1];
        s1.x = acc[co][2]; s1.y = acc[co][3];
        dst[0] = s0;
        dst[1] = s1;
    }
}

extern "C" void kernel_launch(void* const* d_in, const int* in_sizes, int n_in,
                              void* d_out, int out_size) {
    const float* x    = (const float*)d_in[0];
    const float* w    = (const float*)d_in[1];
    const float* bias = (const float*)d_in[2];
    float* out        = (float*)d_out;
    (void)in_sizes; (void)n_in; (void)out_size;
    cudaFuncSetAttribute(bdconv_kernel,
                         cudaFuncAttributeMaxDynamicSharedMemorySize, SMEM_BYTES);
    bdconv_kernel<<<32 * 64 * 16, THREADS, SMEM_BYTES>>>(x, w, bias, out);
}

// round 9
// speedup vs baseline: 1.6392x; 1.6392x over previous
#include <cuda_runtime.h>

// Block-diagonal grouped conv2d: 64 groups, 4 in-ch -> 4 out-ch per group, 3x3, pad 1.
// x:   (32, 256, 128, 128) fp32, channel index = ci*64 + head
// w:   (64, 4, 4, 3, 3)          w[head][co][ci][ky][kx]
// b:   (64, 4)
// out: (32, 256, 128, 128) fp32, channel index = co*64 + head
//
// v9 = v6 with co-pair accumulators: acc u64 = (co0,co1) per pixel; weights in
//      smem as co-pair float2 (3 broadcast LDS.128/iter instead of 6); inputs
//      duplicated (v,v) via mov. TY=8, 128 thr, 7 CTAs/SM, swizzled smem,
//      shuffle edges.

#define TY 8
#define SROWS (TY + 2)               // 10
#define SROW_P 188                   // phys floats per row (swizzle pad)
#define PLANE_P (SROWS * SROW_P)     // 1880
#define S_IN_FLOATS (4 * PLANE_P)    // 7520
#define THREADS 128
#define H 128
#define W 128
#define PLANE (H * W)
// s_in + 72 weight u64 + 2 bias u64
#define SMEM_BYTES ((S_IN_FLOATS) * 4 + 74 * 8)

typedef unsigned long long u64;

__device__ __forceinline__ u64 pk(float lo, float hi) {
    u64 r; asm("mov.b64 %0, {%1, %2};" : "=l"(r) : "f"(lo), "f"(hi)); return r;
}
__device__ __forceinline__ void upk(u64 v, float &lo, float &hi) {
    asm("mov.b64 {%0, %1}, %2;" : "=f"(lo), "=f"(hi) : "l"(v));
}
// d += a*b  (packed 2x fp32)
__device__ __forceinline__ void ffma2(u64 &d, u64 a, u64 b) {
    asm("fma.rn.f32x2 %0, %1, %2, %0;" : "+l"(d) : "l"(a), "l"(b));
}

union F4 { float4 f; ulonglong2 u; };

__global__ __launch_bounds__(THREADS, 7)
void bdconv_kernel(const float* __restrict__ x, const float* __restrict__ w,
                   const float* __restrict__ bias, float* __restrict__ out) {
    extern __shared__ __align__(16) float smem[];
    float* s_in = smem;                          // [ci][r][phys-col]
    u64*   s_w  = (u64*)(smem + S_IN_FLOATS);    // [ci][ky][kx][cp] co-pair float2
    u64*   s_b  = s_w + 72;                      // [cp]

    const int blk  = blockIdx.x;
    const int tile = blk & 15;          // 16 row-tiles of 8
    const int head = (blk >> 4) & 63;
    const int b    = blk >> 10;
    const int y0   = tile * TY;
    const int tid  = threadIdx.x;
    const int wrp  = tid >> 5;
    const int lane = tid & 31;

    // ---- stage weights as co-pair float2 + bias pairs ----
    if (tid < 72) {
        const int cp  = tid & 1;            // co pair: (2cp, 2cp+1)
        const int t9  = (tid >> 1) % 9;     // ky*3+kx
        const int ci  = (tid >> 1) / 9;
        const float w0 = w[((head * 4 + 2 * cp)     * 4 + ci) * 9 + t9];
        const float w1 = w[((head * 4 + 2 * cp + 1) * 4 + ci) * 9 + t9];
        s_w[(ci * 9 + t9) * 2 + cp] = pk(w0, w1);
    }
    if (tid < 2)
        s_b[tid] = pk(bias[head * 4 + 2 * tid], bias[head * 4 + 2 * tid + 1]);

    // ---- stage input: 4 warps x 10 warp-rows (40 = 4ci x 10 rows) ----
    // lane->chunk permutation keeps STS.128 conflict-free under the swizzle:
    //   lanes 0-15  -> even chunks  (phys chunk sigma = 3l)
    //   lanes 16-31 -> odd  chunks  (phys chunk sigma = 3m+1)
    int x0, sig;
    if (lane < 16) { x0 = lane << 3;              sig = 3 * lane; }
    else           { x0 = ((lane - 16) << 3) + 4; sig = 3 * (lane - 16) + 1; }
    const float* xb = x + ((long long)b * 256 + head) * PLANE;   // ci stride 64*PLANE
    #pragma unroll
    for (int k = 0; k < 10; k++) {
        const int rr = wrp + (k << 2);            // 0..39
        const int ci = rr / SROWS;
        const int r  = rr - ci * SROWS;
        const int y  = y0 - 1 + r;
        float4 v = make_float4(0.f, 0.f, 0.f, 0.f);
        if (y >= 0 && y < H)
            v = *(const float4*)(xb + ci * (64 * PLANE) + y * W + x0);
        *(float4*)(s_in + ci * PLANE_P + r * SROW_P + (sig << 2)) = v;
    }
    __syncthreads();

    // ---- compute: each thread = 8 pixels x 4 out-channels (co-pair acc) ----
    const int r  = tid >> 4;           // row within tile, 0..7
    const int j  = tid & 15;           // pixel-octet index, x = 8j..8j+7
    const int base = r * SROW_P + 12 * j;   // phys(8j) = 12j

    u64 acc0[8], acc1[8];              // acc0: (co0,co1), acc1: (co2,co3)
    {
        const u64 b0 = s_b[0];
        const u64 b1 = s_b[1];
        #pragma unroll
        for (int px = 0; px < 8; px++) { acc0[px] = b0; acc1[px] = b1; }
    }

    #pragma unroll
    for (int ci = 0; ci < 4; ci++) {
        #pragma unroll
        for (int ky = 0; ky < 3; ky++) {
            const int imm = ci * PLANE_P + ky * SROW_P;   // compile-time
            F4 B, C;
            B.f = *(const float4*)(s_in + imm + base);
            C.f = *(const float4*)(s_in + imm + base + 4);

            // window edges from neighbor lanes (zero at x-boundaries)
            float A = __shfl_up_sync(0xffffffffu, C.f.w, 1);
            float D = __shfl_down_sync(0xffffffffu, B.f.x, 1);
            if (j == 0)  A = 0.0f;
            if (j == 15) D = 0.0f;

            // duplicated window values x(8j-1 .. 8j+8)
            u64 dv[10];
            dv[0] = pk(A, A);
            dv[1] = pk(B.f.x, B.f.x);
            dv[2] = pk(B.f.y, B.f.y);
            dv[3] = pk(B.f.z, B.f.z);
            dv[4] = pk(B.f.w, B.f.w);
            dv[5] = pk(C.f.x, C.f.x);
            dv[6] = pk(C.f.y, C.f.y);
            dv[7] = pk(C.f.z, C.f.z);
            dv[8] = pk(C.f.w, C.f.w);
            dv[9] = pk(D, D);

            // weights: 3 x LDS.128 uniform broadcast -> [kx](cp0,cp1)
            const ulonglong2* wp = (const ulonglong2*)(s_w + (ci * 9 + ky * 3) * 2);
            ulonglong2 wv[3];
            #pragma unroll
            for (int t = 0; t < 3; t++) wv[t] = wp[t];

            // 48 packed FMAs
            #pragma unroll
            for (int px = 0; px < 8; px++)
                #pragma unroll
                for (int kx = 0; kx < 3; kx++) {
                    const u64 in = dv[px + kx];
                    ffma2(acc0[px], wv[kx].x, in);
                    ffma2(acc1[px], wv[kx].y, in);
                }
        }
    }

    // ---- store: transpose co-pairs -> 2x STG.128 per co ----
    const int y = y0 + r;
    float* obase = out + (((long long)b * 256 + head) * H + y) * W + (j << 3);
    {
        float lo[8], hi[8];
        #pragma unroll
        for (int px = 0; px < 8; px++) upk(acc0[px], lo[px], hi[px]);
        float4* d0 = (float4*)(obase);                      // co = 0
        float4* d1 = (float4*)(obase + (long long)64 * PLANE);   // co = 1
        d0[0] = make_float4(lo[0], lo[1], lo[2], lo[3]);
        d0[1] = make_float4(lo[4], lo[5], lo[6], lo[7]);
        d1[0] = make_float4(hi[0], hi[1], hi[2], hi[3]);
        d1[1] = make_float4(hi[4], hi[5], hi[6], hi[7]);
        #pragma unroll
        for (int px = 0; px < 8; px++) upk(acc1[px], lo[px], hi[px]);
        float4* d2 = (float4*)(obase + (long long)128 * PLANE);  // co = 2
        float4* d3 = (float4*)(obase + (long long)192 * PLANE);  // co = 3
        d2[0] = make_float4(lo[0], lo[1], lo[2], lo[3]);
        d2[1] = make_float4(lo[4], lo[5], lo[6], lo[7]);
        d3[0] = make_float4(hi[0], hi[1], hi[2], hi[3]);
        d3[1] = make_float4(hi[4], hi[5], hi[6], hi[7]);
    }
}

extern "C" void kernel_launch(void* const* d_in, const int* in_sizes, int n_in,
                              void* d_out, int out_size) {
    const float* x    = (const float*)d_in[0];
    const float* w    = (const float*)d_in[1];
    const float* bias = (const float*)d_in[2];
    float* out        = (float*)d_out;
    (void)in_sizes; (void)n_in; (void)out_size;
    cudaFuncSetAttribute(bdconv_kernel,
                         cudaFuncAttributeMaxDynamicSharedMemorySize, SMEM_BYTES);
    bdconv_kernel<<<32 * 64 * 16, THREADS, SMEM_BYTES>>>(x, w, bias, out);
}

// round 10
// speedup vs baseline: 1.9260x; 1.1749x over previous
#include <cuda_runtime.h>

// Block-diagonal grouped conv2d: 64 groups, 4 in-ch -> 4 out-ch per group, 3x3, pad 1.
// x:   (32, 256, 128, 128) fp32, channel index = ci*64 + head
// w:   (64, 4, 4, 3, 3)          w[head][co][ci][ky][kx]
// b:   (64, 4)
// out: (32, 256, 128, 128) fp32, channel index = co*64 + head
//
// v10: occupancy build. 256 threads, TY=8, warp = one output row, thread =
//      4 px x 4 co (co-pair f32x2 accs, 8 u64). Row-major smem (no swizzle
//      needed: lane l covers quad l -> conflict-free). 5 CTAs/SM, 40 warps.

#define TY 8
#define SROWS (TY + 2)               // 10
#define SROW_P 132                   // row stride (floats); only 128 used
#define PLANE_P (SROWS * SROW_P)     // 1320
#define S_IN_FLOATS (4 * PLANE_P)    // 5280
#define THREADS 256
#define H 128
#define W 128
#define PLANE (H * W)
// s_in + 72 weight u64 + 2 bias u64
#define SMEM_BYTES (S_IN_FLOATS * 4 + 74 * 8)

typedef unsigned long long u64;

__device__ __forceinline__ u64 pk(float lo, float hi) {
    u64 r; asm("mov.b64 %0, {%1, %2};" : "=l"(r) : "f"(lo), "f"(hi)); return r;
}
__device__ __forceinline__ void upk(u64 v, float &lo, float &hi) {
    asm("mov.b64 {%0, %1}, %2;" : "=f"(lo), "=f"(hi) : "l"(v));
}
// d += a*b  (packed 2x fp32)
__device__ __forceinline__ void ffma2(u64 &d, u64 a, u64 b) {
    asm("fma.rn.f32x2 %0, %1, %2, %0;" : "+l"(d) : "l"(a), "l"(b));
}

__global__ __launch_bounds__(THREADS, 5)
void bdconv_kernel(const float* __restrict__ x, const float* __restrict__ w,
                   const float* __restrict__ bias, float* __restrict__ out) {
    extern __shared__ __align__(16) float smem[];
    float* s_in = smem;                          // [ci][r][col], row-major
    u64*   s_w  = (u64*)(smem + S_IN_FLOATS);    // [ci][ky][kx][cp] co-pair
    u64*   s_b  = s_w + 72;                      // [cp]

    const int blk  = blockIdx.x;
    const int tile = blk & 15;          // 16 row-tiles of 8
    const int head = (blk >> 4) & 63;
    const int b    = blk >> 10;
    const int y0   = tile * TY;
    const int tid  = threadIdx.x;
    const int wrp  = tid >> 5;
    const int lane = tid & 31;

    // ---- stage weights as co-pair float2 + bias pairs ----
    if (tid < 72) {
        const int cp  = tid & 1;            // co pair: (2cp, 2cp+1)
        const int t9  = (tid >> 1) % 9;     // ky*3+kx
        const int ci  = (tid >> 1) / 9;
        const float w0 = w[((head * 4 + 2 * cp)     * 4 + ci) * 9 + t9];
        const float w1 = w[((head * 4 + 2 * cp + 1) * 4 + ci) * 9 + t9];
        s_w[(ci * 9 + t9) * 2 + cp] = pk(w0, w1);
    }
    if (tid < 2)
        s_b[tid] = pk(bias[head * 4 + 2 * tid], bias[head * 4 + 2 * tid + 1]);

    // ---- stage input: 8 warps x 5 (ci,row) pairs; lane l -> float4 at 4l ----
    {
        const float* xb = x + ((long long)b * 256 + head) * PLANE;  // ci stride 64*PLANE
        const int xo = lane << 2;
        #pragma unroll
        for (int k = 0; k < 5; k++) {
            const int rr = wrp + (k << 3);            // 0..39
            const int ci = rr / SROWS;
            const int r  = rr - ci * SROWS;
            const int y  = y0 - 1 + r;
            float4 v = make_float4(0.f, 0.f, 0.f, 0.f);
            if (y >= 0 && y < H)
                v = *(const float4*)(xb + ci * (64 * PLANE) + y * W + xo);
            *(float4*)(s_in + ci * PLANE_P + r * SROW_P + xo) = v;
        }
    }
    __syncthreads();

    // ---- compute: thread = 4 px x 4 co; warp = output row wrp ----
    u64 acc0[4], acc1[4];              // acc0: (co0,co1), acc1: (co2,co3)
    {
        const u64 b0 = s_b[0];
        const u64 b1 = s_b[1];
        #pragma unroll
        for (int q = 0; q < 4; q++) { acc0[q] = b0; acc1[q] = b1; }
    }

    const float* plane0 = s_in + wrp * SROW_P + (lane << 2);
    const u64*   wci    = s_w;

    #pragma unroll 1
    for (int ci = 0; ci < 4; ci++) {
        #pragma unroll
        for (int ky = 0; ky < 3; ky++) {
            float4 B = *(const float4*)(plane0 + ky * SROW_P);

            // window edges x=4l-1 and x=4l+4 from neighbor lanes
            float A = __shfl_up_sync(0xffffffffu, B.w, 1);
            float E = __shfl_down_sync(0xffffffffu, B.x, 1);
            if (lane == 0)  A = 0.0f;     // x = -1
            if (lane == 31) E = 0.0f;     // x = 128

            // duplicated window values x(4l-1 .. 4l+4)
            u64 dv[6];
            dv[0] = pk(A, A);
            dv[1] = pk(B.x, B.x);
            dv[2] = pk(B.y, B.y);
            dv[3] = pk(B.z, B.z);
            dv[4] = pk(B.w, B.w);
            dv[5] = pk(E, E);

            // weights: 3 x LDS.128 uniform broadcast -> [kx](cp0,cp1)
            const ulonglong2* wp = (const ulonglong2*)(wci + ky * 6);
            ulonglong2 wv0 = wp[0], wv1 = wp[1], wv2 = wp[2];

            // 24 packed FMAs
            #pragma unroll
            for (int q = 0; q < 4; q++) {
                ffma2(acc0[q], wv0.x, dv[q]);
                ffma2(acc1[q], wv0.y, dv[q]);
                ffma2(acc0[q], wv1.x, dv[q + 1]);
                ffma2(acc1[q], wv1.y, dv[q + 1]);
                ffma2(acc0[q], wv2.x, dv[q + 2]);
                ffma2(acc1[q], wv2.y, dv[q + 2]);
            }
        }
        plane0 += PLANE_P;
        wci    += 18;
    }

    // ---- store: 4x STG.128 (one per co), coalesced across the warp ----
    const int y = y0 + wrp;
    float* obase = out + (((long long)b * 256 + head) * H + y) * W + (lane << 2);
    {
        float l0[4], h0[4], l1[4], h1[4];
        #pragma unroll
        for (int q = 0; q < 4; q++) { upk(acc0[q], l0[q], h0[q]); upk(acc1[q], l1[q], h1[q]); }
        *(float4*)(obase)                           = make_float4(l0[0], l0[1], l0[2], l0[3]);
        *(float4*)(obase + (long long) 64 * PLANE)  = make_float4(h0[0], h0[1], h0[2], h0[3]);
        *(float4*)(obase + (long long)128 * PLANE)  = make_float4(l1[0], l1[1], l1[2], l1[3]);
        *(float4*)(obase + (long long)192 * PLANE)  = make_float4(h1[0], h1[1], h1[2], h1[3]);
    }
}

extern "C" void kernel_launch(void* const* d_in, const int* in_sizes, int n_in,
                              void* d_out, int out_size) {
    const float* x    = (const float*)d_in[0];
    const float* w    = (const float*)d_in[1];
    const float* bias = (const float*)d_in[2];
    float* out        = (float*)d_out;
    (void)in_sizes; (void)n_in; (void)out_size;
    cudaFuncSetAttribute(bdconv_kernel,
                         cudaFuncAttributeMaxDynamicSharedMemorySize, SMEM_BYTES);
    bdconv_kernel<<<32 * 64 * 16, THREADS, SMEM_BYTES>>>(x, w, bias, out);
}

// round 11
// speedup vs baseline: 2.1203x; 1.1009x over previous
#include <cuda_runtime.h>

// Block-diagonal grouped conv2d: 64 groups, 4 in-ch -> 4 out-ch per group, 3x3, pad 1.
// x:   (32, 256, 128, 128) fp32, channel index = ci*64 + head
// w:   (64, 4, 4, 3, 3)          w[head][co][ci][ky][kx]
// b:   (64, 4)
// out: (32, 256, 128, 128) fp32, channel index = co*64 + head
//
// v11: 2 output rows per thread (warp = row pair), ky-outer loop so each
//      weight-set broadcast feeds both rows (weight LDS halved per row).
//      TY=16 (12.5% halo), 256 threads, co-pair f32x2 accs, 4 CTAs/SM.

#define TY 16
#define SROWS (TY + 2)               // 18
#define SROW_P 132                   // row stride (floats); only 128 used
#define PLANE_P (SROWS * SROW_P)     // 2376
#define S_IN_FLOATS (4 * PLANE_P)    // 9504
#define THREADS 256
#define H 128
#define W 128
#define PLANE (H * W)
// s_in + 72 weight u64 + 2 bias u64
#define SMEM_BYTES (S_IN_FLOATS * 4 + 74 * 8)

typedef unsigned long long u64;

__device__ __forceinline__ u64 pk(float lo, float hi) {
    u64 r; asm("mov.b64 %0, {%1, %2};" : "=l"(r) : "f"(lo), "f"(hi)); return r;
}
__device__ __forceinline__ void upk(u64 v, float &lo, float &hi) {
    asm("mov.b64 {%0, %1}, %2;" : "=f"(lo), "=f"(hi) : "l"(v));
}
// d += a*b  (packed 2x fp32)
__device__ __forceinline__ void ffma2(u64 &d, u64 a, u64 b) {
    asm("fma.rn.f32x2 %0, %1, %2, %0;" : "+l"(d) : "l"(a), "l"(b));
}

__global__ __launch_bounds__(THREADS, 4)
void bdconv_kernel(const float* __restrict__ x, const float* __restrict__ w,
                   const float* __restrict__ bias, float* __restrict__ out) {
    extern __shared__ __align__(16) float smem[];
    float* s_in = smem;                          // [ci][r][col], row-major
    u64*   s_w  = (u64*)(smem + S_IN_FLOATS);    // [ci][ky][kx][cp] co-pair
    u64*   s_b  = s_w + 72;                      // [cp]

    const int blk  = blockIdx.x;
    const int tile = blk & 7;           // 8 row-tiles of 16
    const int head = (blk >> 3) & 63;
    const int b    = blk >> 9;
    const int y0   = tile * TY;
    const int tid  = threadIdx.x;
    const int wrp  = tid >> 5;
    const int lane = tid & 31;

    // ---- stage weights as co-pair float2 + bias pairs ----
    if (tid < 72) {
        const int cp  = tid & 1;            // co pair: (2cp, 2cp+1)
        const int t9  = (tid >> 1) % 9;     // ky*3+kx
        const int ci  = (tid >> 1) / 9;
        const float w0 = w[((head * 4 + 2 * cp)     * 4 + ci) * 9 + t9];
        const float w1 = w[((head * 4 + 2 * cp + 1) * 4 + ci) * 9 + t9];
        s_w[(ci * 9 + t9) * 2 + cp] = pk(w0, w1);
    }
    if (tid < 2)
        s_b[tid] = pk(bias[head * 4 + 2 * tid], bias[head * 4 + 2 * tid + 1]);

    // ---- stage input: 8 warps x 9 (ci,row) pairs; lane l -> float4 at 4l ----
    {
        const float* xb = x + ((long long)b * 256 + head) * PLANE;  // ci stride 64*PLANE
        const int xo = lane << 2;
        #pragma unroll
        for (int k = 0; k < 9; k++) {
            const int rr = wrp + (k << 3);            // 0..71
            const int ci = rr / SROWS;
            const int r  = rr - ci * SROWS;
            const int y  = y0 - 1 + r;
            float4 v = make_float4(0.f, 0.f, 0.f, 0.f);
            if (y >= 0 && y < H)
                v = *(const float4*)(xb + ci * (64 * PLANE) + y * W + xo);
            *(float4*)(s_in + ci * PLANE_P + r * SROW_P + xo) = v;
        }
    }
    __syncthreads();

    // ---- compute: warp = output rows (2*wrp, 2*wrp+1); thread = 4 px x 4 co x 2 rows ----
    u64 acc0[2][4], acc1[2][4];        // [row][q]; acc0=(co0,co1), acc1=(co2,co3)
    {
        const u64 b0 = s_b[0];
        const u64 b1 = s_b[1];
        #pragma unroll
        for (int rw = 0; rw < 2; rw++)
            #pragma unroll
            for (int q = 0; q < 4; q++) { acc0[rw][q] = b0; acc1[rw][q] = b1; }
    }

    const float* pl0 = s_in + (2 * wrp) * SROW_P + (lane << 2);
    const u64*   wci = s_w;

    #pragma unroll 1
    for (int ci = 0; ci < 4; ci++) {
        #pragma unroll
        for (int ky = 0; ky < 3; ky++) {
            // weight-set for this ky, shared by both output rows
            const ulonglong2* wp = (const ulonglong2*)(wci + ky * 6);
            const ulonglong2 wv0 = wp[0], wv1 = wp[1], wv2 = wp[2];

            #pragma unroll
            for (int rw = 0; rw < 2; rw++) {
                // input smem row = (2*wrp + rw) + ky
                float4 B = *(const float4*)(pl0 + (rw + ky) * SROW_P);

                float A = __shfl_up_sync(0xffffffffu, B.w, 1);
                float E = __shfl_down_sync(0xffffffffu, B.x, 1);
                if (lane == 0)  A = 0.0f;     // x = -1
                if (lane == 31) E = 0.0f;     // x = 128

                u64 dv[6];
                dv[0] = pk(A, A);
                dv[1] = pk(B.x, B.x);
                dv[2] = pk(B.y, B.y);
                dv[3] = pk(B.z, B.z);
                dv[4] = pk(B.w, B.w);
                dv[5] = pk(E, E);

                #pragma unroll
                for (int q = 0; q < 4; q++) {
                    ffma2(acc0[rw][q], wv0.x, dv[q]);
                    ffma2(acc1[rw][q], wv0.y, dv[q]);
                    ffma2(acc0[rw][q], wv1.x, dv[q + 1]);
                    ffma2(acc1[rw][q], wv1.y, dv[q + 1]);
                    ffma2(acc0[rw][q], wv2.x, dv[q + 2]);
                    ffma2(acc1[rw][q], wv2.y, dv[q + 2]);
                }
            }
        }
        pl0 += PLANE_P;
        wci += 18;
    }

    // ---- store: 2 rows x 4 co, STG.128 coalesced across the warp ----
    #pragma unroll
    for (int rw = 0; rw < 2; rw++) {
        const int y = y0 + 2 * wrp + rw;
        float* obase = out + (((long long)b * 256 + head) * H + y) * W + (lane << 2);
        float l0[4], h0[4], l1[4], h1[4];
        #pragma unroll
        for (int q = 0; q < 4; q++) {
            upk(acc0[rw][q], l0[q], h0[q]);
            upk(acc1[rw][q], l1[q], h1[q]);
        }
        *(float4*)(obase)                          = make_float4(l0[0], l0[1], l0[2], l0[3]);
        *(float4*)(obase + (long long) 64 * PLANE) = make_float4(h0[0], h0[1], h0[2], h0[3]);
        *(float4*)(obase + (long long)128 * PLANE) = make_float4(l1[0], l1[1], l1[2], l1[3]);
        *(float4*)(obase + (long long)192 * PLANE) = make_float4(h1[0], h1[1], h1[2], h1[3]);
    }
}

extern "C" void kernel_launch(void* const* d_in, const int* in_sizes, int n_in,
                              void* d_out, int out_size) {
    const float* x    = (const float*)d_in[0];
    const float* w    = (const float*)d_in[1];
    const float* bias = (const float*)d_in[2];
    float* out        = (float*)d_out;
    (void)in_sizes; (void)n_in; (void)out_size;
    cudaFuncSetAttribute(bdconv_kernel,
                         cudaFuncAttributeMaxDynamicSharedMemorySize, SMEM_BYTES);
    bdconv_kernel<<<32 * 64 * 8, THREADS, SMEM_BYTES>>>(x, w, bias, out);
}

// round 12
// speedup vs baseline: 2.4213x; 1.1420x over previous
#include <cuda_runtime.h>
#include <cstdint>

// Block-diagonal grouped conv2d: 64 groups, 4 in-ch -> 4 out-ch per group, 3x3, pad 1.
// x:   (32, 256, 128, 128) fp32, channel index = ci*64 + head
// w:   (64, 4, 4, 3, 3)          w[head][co][ci][ky][kx]
// b:   (64, 4)
// out: (32, 256, 128, 128) fp32, channel index = co*64 + head
//
// v12: phase-overlap build. 128-thread CTAs, TY=8, 8 CTAs/SM (32 warps, 8
//      independent phase-staggered tiles per SM), cp.async staging (no
//      LDG->STS register round-trip), v11 compute core (co-pair f32x2 accs,
//      ky-outer weight reuse across 2 rows per warp).

#define TY 8
#define SROWS (TY + 2)               // 10
#define SROW_P 132                   // row stride (floats); only 128 used
#define PLANE_P (SROWS * SROW_P)     // 1320
#define S_IN_FLOATS (4 * PLANE_P)    // 5280
#define THREADS 128
#define H 128
#define W 128
#define PLANE (H * W)
// s_in + 72 weight u64 + 2 bias u64
#define SMEM_BYTES (S_IN_FLOATS * 4 + 74 * 8)

typedef unsigned long long u64;

__device__ __forceinline__ u64 pk(float lo, float hi) {
    u64 r; asm("mov.b64 %0, {%1, %2};" : "=l"(r) : "f"(lo), "f"(hi)); return r;
}
__device__ __forceinline__ void upk(u64 v, float &lo, float &hi) {
    asm("mov.b64 {%0, %1}, %2;" : "=f"(lo), "=f"(hi) : "l"(v));
}
// d += a*b  (packed 2x fp32)
__device__ __forceinline__ void ffma2(u64 &d, u64 a, u64 b) {
    asm("fma.rn.f32x2 %0, %1, %2, %0;" : "+l"(d) : "l"(a), "l"(b));
}
__device__ __forceinline__ void cpasync16(uint32_t saddr, const float* g, bool pred) {
    int sz = pred ? 16 : 0;
    asm volatile("cp.async.cg.shared.global [%0], [%1], 16, %2;\n"
                 :: "r"(saddr), "l"(g), "r"(sz));
}

__global__ __launch_bounds__(THREADS, 8)
void bdconv_kernel(const float* __restrict__ x, const float* __restrict__ w,
                   const float* __restrict__ bias, float* __restrict__ out) {
    extern __shared__ __align__(16) float smem[];
    float* s_in = smem;                          // [ci][r][col], row-major
    u64*   s_w  = (u64*)(smem + S_IN_FLOATS);    // [ci][ky][kx][cp] co-pair
    u64*   s_b  = s_w + 72;                      // [cp]

    const int blk  = blockIdx.x;
    const int tile = blk & 15;          // 16 row-tiles of 8
    const int head = (blk >> 4) & 63;
    const int b    = blk >> 10;
    const int y0   = tile * TY;
    const int tid  = threadIdx.x;
    const int wrp  = tid >> 5;
    const int lane = tid & 31;

    // ---- stage input via cp.async: 4 warps x 10 (ci,row) pairs ----
    {
        const float* xb = x + ((long long)b * 256 + head) * PLANE;  // ci stride 64*PLANE
        const int xo = lane << 2;
        const uint32_t sbase =
            (uint32_t)__cvta_generic_to_shared(s_in) + (uint32_t)(xo * 4);
        #pragma unroll
        for (int k = 0; k < 10; k++) {
            const int rr = wrp + (k << 2);            // 0..39
            const int ci = rr / SROWS;
            const int r  = rr - ci * SROWS;
            const int y  = y0 - 1 + r;
            const bool ok = (y >= 0) && (y < H);
            const int yc = ok ? y : 0;
            cpasync16(sbase + (uint32_t)((ci * PLANE_P + r * SROW_P) * 4),
                      xb + ci * (64 * PLANE) + yc * W + xo, ok);
        }
        asm volatile("cp.async.commit_group;\n");
    }

    // ---- stage weights as co-pair float2 + bias pairs (regular LDS path) ----
    if (tid < 72) {
        const int cp  = tid & 1;            // co pair: (2cp, 2cp+1)
        const int t9  = (tid >> 1) % 9;     // ky*3+kx
        const int ci  = (tid >> 1) / 9;
        const float w0 = w[((head * 4 + 2 * cp)     * 4 + ci) * 9 + t9];
        const float w1 = w[((head * 4 + 2 * cp + 1) * 4 + ci) * 9 + t9];
        s_w[(ci * 9 + t9) * 2 + cp] = pk(w0, w1);
    }
    if (tid < 2)
        s_b[tid] = pk(bias[head * 4 + 2 * tid], bias[head * 4 + 2 * tid + 1]);

    asm volatile("cp.async.wait_group 0;\n");
    __syncthreads();

    // ---- compute: warp = output rows (2*wrp, 2*wrp+1); thread = 4 px x 4 co x 2 rows ----
    u64 acc0[2][4], acc1[2][4];        // [row][q]; acc0=(co0,co1), acc1=(co2,co3)
    {
        const u64 b0 = s_b[0];
        const u64 b1 = s_b[1];
        #pragma unroll
        for (int rw = 0; rw < 2; rw++)
            #pragma unroll
            for (int q = 0; q < 4; q++) { acc0[rw][q] = b0; acc1[rw][q] = b1; }
    }

    const float* pl0 = s_in + (2 * wrp) * SROW_P + (lane << 2);
    const u64*   wci = s_w;

    #pragma unroll 1
    for (int ci = 0; ci < 4; ci++) {
        #pragma unroll
        for (int ky = 0; ky < 3; ky++) {
            // weight-set for this ky, shared by both output rows
            const ulonglong2* wp = (const ulonglong2*)(wci + ky * 6);
            const ulonglong2 wv0 = wp[0], wv1 = wp[1], wv2 = wp[2];

            #pragma unroll
            for (int rw = 0; rw < 2; rw++) {
                // input smem row = (2*wrp + rw) + ky
                float4 B = *(const float4*)(pl0 + (rw + ky) * SROW_P);

                float A = __shfl_up_sync(0xffffffffu, B.w, 1);
                float E = __shfl_down_sync(0xffffffffu, B.x, 1);
                if (lane == 0)  A = 0.0f;     // x = -1
                if (lane == 31) E = 0.0f;     // x = 128

                u64 dv[6];
                dv[0] = pk(A, A);
                dv[1] = pk(B.x, B.x);
                dv[2] = pk(B.y, B.y);
                dv[3] = pk(B.z, B.z);
                dv[4] = pk(B.w, B.w);
                dv[5] = pk(E, E);

                #pragma unroll
                for (int q = 0; q < 4; q++) {
                    ffma2(acc0[rw][q], wv0.x, dv[q]);
                    ffma2(acc1[rw][q], wv0.y, dv[q]);
                    ffma2(acc0[rw][q], wv1.x, dv[q + 1]);
                    ffma2(acc1[rw][q], wv1.y, dv[q + 1]);
                    ffma2(acc0[rw][q], wv2.x, dv[q + 2]);
                    ffma2(acc1[rw][q], wv2.y, dv[q + 2]);
                }
            }
        }
        pl0 += PLANE_P;
        wci += 18;
    }

    // ---- store: 2 rows x 4 co, STG.128 coalesced across the warp ----
    #pragma unroll
    for (int rw = 0; rw < 2; rw++) {
        const int y = y0 + 2 * wrp + rw;
        float* obase = out + (((long long)b * 256 + head) * H + y) * W + (lane << 2);
        float l0[4], h0[4], l1[4], h1[4];
        #pragma unroll
        for (int q = 0; q < 4; q++) {
            upk(acc0[rw][q], l0[q], h0[q]);
            upk(acc1[rw][q], l1[q], h1[q]);
        }
        *(float4*)(obase)                          = make_float4(l0[0], l0[1], l0[2], l0[3]);
        *(float4*)(obase + (long long) 64 * PLANE) = make_float4(h0[0], h0[1], h0[2], h0[3]);
        *(float4*)(obase + (long long)128 * PLANE) = make_float4(l1[0], l1[1], l1[2], l1[3]);
        *(float4*)(obase + (long long)192 * PLANE) = make_float4(h1[0], h1[1], h1[2], h1[3]);
    }
}

extern "C" void kernel_launch(void* const* d_in, const int* in_sizes, int n_in,
                              void* d_out, int out_size) {
    const float* x    = (const float*)d_in[0];
    const float* w    = (const float*)d_in[1];
    const float* bias = (const float*)d_in[2];
    float* out        = (float*)d_out;
    (void)in_sizes; (void)n_in; (void)out_size;
    cudaFuncSetAttribute(bdconv_kernel,
                         cudaFuncAttributeMaxDynamicSharedMemorySize, SMEM_BYTES);
    bdconv_kernel<<<32 * 64 * 16, THREADS, SMEM_BYTES>>>(x, w, bias, out);
}